// round 1
// baseline (speedup 1.0000x reference)
#include <cuda_runtime.h>
#include <cstdint>
#include <cstddef>

#define B_   4
#define T_   1024
#define H_   32
#define KVH_ 8
#define HD_  128
#define DM_  4096
#define NTOK (B_ * T_)

// Scratch (device globals — no runtime allocation allowed)
__device__ float g_q[(size_t)NTOK * DM_];     // 64 MB : q after proj+rope, [n][h*128+d]
__device__ float g_kv[(size_t)NTOK * 2048];   // 32 MB : [n][ k(8*128) | v(8*128) ]
__device__ float g_att[(size_t)NTOK * DM_];   // 64 MB : attention output [n][h*128+d]

// ---------------------------------------------------------------------------
// helpers
// ---------------------------------------------------------------------------
__device__ __forceinline__ uint32_t f2tf(float x) {
    uint32_t r;
    asm("cvt.rna.tf32.f32 %0, %1;" : "=r"(r) : "f"(x));
    return r;
}

__device__ __forceinline__ void mma_tf32(float d[4], const uint32_t a[4],
                                         uint32_t b0, uint32_t b1) {
    asm volatile(
        "mma.sync.aligned.m16n8k8.row.col.f32.tf32.tf32.f32 "
        "{%0,%1,%2,%3}, {%4,%5,%6,%7}, {%8,%9}, {%0,%1,%2,%3};\n"
        : "+f"(d[0]), "+f"(d[1]), "+f"(d[2]), "+f"(d[3])
        : "r"(a[0]), "r"(a[1]), "r"(a[2]), "r"(a[3]), "r"(b0), "r"(b1));
}

// ---------------------------------------------------------------------------
// tf32 GEMM: C[M,N] = A[M,K] @ B[K,N], all fp32 row-major.
// 128x128 tile, BK=32, 256 threads (8 warps, 4x2), warp tile 32x64.
// ---------------------------------------------------------------------------
#define GBM 128
#define GBN 128
#define GBK 32

__global__ void __launch_bounds__(256)
gemm_tf32_kernel(const float* __restrict__ A, const float* __restrict__ B,
                 float* __restrict__ C, int M, int N, int K) {
    __shared__ float As[GBM][GBK + 4];  // 128 x 36
    __shared__ float Bs[GBK][GBN + 4];  // 32  x 132

    const int bx = blockIdx.x;   // N tile
    const int by = blockIdx.y;   // M tile
    const int tid  = threadIdx.x;
    const int warp = tid >> 5;
    const int lane = tid & 31;
    const int wm = warp & 3;     // 0..3 -> rows wm*32
    const int wn = warp >> 2;    // 0..1 -> cols wn*64
    const int gr = lane >> 2;    // group row 0..7
    const int tg = lane & 3;     // thread-in-group 0..3

    float acc[2][8][4];
    #pragma unroll
    for (int mt = 0; mt < 2; mt++)
        #pragma unroll
        for (int nt = 0; nt < 8; nt++)
            #pragma unroll
            for (int e = 0; e < 4; e++) acc[mt][nt][e] = 0.f;

    // global->smem load indices
    const int arow  = tid >> 3;       // 0..31 (+i*32)
    const int acol4 = tid & 7;        // float4 col 0..7
    const int brow  = tid >> 5;       // 0..7 (+i*8)
    const int bcol4 = tid & 31;       // float4 col 0..31

    for (int kt = 0; kt < K; kt += GBK) {
        #pragma unroll
        for (int i = 0; i < 4; i++) {
            int r = arow + i * 32;
            float4 v = *(const float4*)&A[(size_t)(by * GBM + r) * K + kt + acol4 * 4];
            *(float4*)&As[r][acol4 * 4] = v;
        }
        #pragma unroll
        for (int i = 0; i < 4; i++) {
            int r = brow + i * 8;
            float4 v = *(const float4*)&B[(size_t)(kt + r) * N + bx * GBN + bcol4 * 4];
            *(float4*)&Bs[r][bcol4 * 4] = v;
        }
        __syncthreads();

        #pragma unroll
        for (int ks = 0; ks < GBK / 8; ks++) {
            uint32_t af[2][4];
            #pragma unroll
            for (int mt = 0; mt < 2; mt++) {
                int r0 = wm * 32 + mt * 16 + gr;
                int c0 = ks * 8 + tg;
                af[mt][0] = f2tf(As[r0][c0]);
                af[mt][1] = f2tf(As[r0 + 8][c0]);
                af[mt][2] = f2tf(As[r0][c0 + 4]);
                af[mt][3] = f2tf(As[r0 + 8][c0 + 4]);
            }
            #pragma unroll
            for (int nt = 0; nt < 8; nt++) {
                int cc = wn * 64 + nt * 8 + gr;
                int rr = ks * 8 + tg;
                uint32_t b0 = f2tf(Bs[rr][cc]);
                uint32_t b1 = f2tf(Bs[rr + 4][cc]);
                mma_tf32(acc[0][nt], af[0], b0, b1);
                mma_tf32(acc[1][nt], af[1], b0, b1);
            }
        }
        __syncthreads();
    }

    // epilogue
    #pragma unroll
    for (int mt = 0; mt < 2; mt++)
        #pragma unroll
        for (int nt = 0; nt < 8; nt++)
            #pragma unroll
            for (int e = 0; e < 4; e++) {
                int row = by * GBM + wm * 32 + mt * 16 + gr + ((e >= 2) ? 8 : 0);
                int col = bx * GBN + wn * 64 + nt * 8 + 2 * tg + (e & 1);
                C[(size_t)row * N + col] = acc[mt][nt][e];
            }
}

// ---------------------------------------------------------------------------
// RoPE (in place): buf[n*rowstride + h*128 + {2i,2i+1}]
// ---------------------------------------------------------------------------
__global__ void rope_kernel(float* __restrict__ buf, const float* __restrict__ rcos,
                            const float* __restrict__ rsin,
                            const int* __restrict__ positions,
                            int nheads, int rowstride) {
    int idx = blockIdx.x * blockDim.x + threadIdx.x;
    int total = NTOK * nheads * 64;
    if (idx >= total) return;
    int i = idx & 63;
    int h = (idx >> 6) % nheads;
    int n = idx / (64 * nheads);
    int pos = positions[n];
    float c = rcos[pos * 64 + i];
    float s = rsin[pos * 64 + i];
    float2* p = (float2*)(buf + (size_t)n * rowstride + h * 128 + 2 * i);
    float2 v = *p;
    float2 o;
    o.x = v.x * c - v.y * s;
    o.y = v.x * s + v.y * c;
    *p = o;
}

// ---------------------------------------------------------------------------
// Flash attention, causal, GQA (4 q-heads per kv-head), tf32 mma.
// grid = (T/64, H, B), block = 128 (4 warps). Each block: 64 q rows, 1 head.
// SMEM (dynamic): Qs[64][132] Ks[64][132] Vs[64][132] Ps[64][68]
// ---------------------------------------------------------------------------
#define ATT_SMEM_FLOATS (3 * 64 * 132 + 64 * 68)

__global__ void __launch_bounds__(128)
attn_kernel(const float* __restrict__ q, const float* __restrict__ kv,
            float* __restrict__ out) {
    extern __shared__ float sm[];
    float* Qs = sm;                    // 64*132
    float* Ks = Qs + 64 * 132;
    float* Vs = Ks + 64 * 132;
    float* Ps = Vs + 64 * 132;         // 64*68

    const int m0  = blockIdx.x * 64;
    const int h   = blockIdx.y;
    const int b   = blockIdx.z;
    const int kvh = h >> 2;            // NREP = 4
    const int tid  = threadIdx.x;
    const int warp = tid >> 5;
    const int lane = tid & 31;
    const int gr = lane >> 2;
    const int tg = lane & 3;

    // load Q tile -> Qs (coalesced)
    for (int i = tid; i < 64 * 32; i += 128) {
        int r = i >> 5, c4 = i & 31;
        float4 v = *(const float4*)&q[((size_t)(b * T_ + m0 + r) * H_ + h) * HD_ + c4 * 4];
        *(float4*)&Qs[r * 132 + c4 * 4] = v;
    }
    __syncthreads();

    // Q fragments (16 k-steps over d=128), pre-converted to tf32
    uint32_t qf[16][4];
    #pragma unroll
    for (int ks = 0; ks < 16; ks++) {
        int r0 = warp * 16 + gr;
        int c0 = ks * 8 + tg;
        qf[ks][0] = f2tf(Qs[r0 * 132 + c0]);
        qf[ks][1] = f2tf(Qs[(r0 + 8) * 132 + c0]);
        qf[ks][2] = f2tf(Qs[r0 * 132 + c0 + 4]);
        qf[ks][3] = f2tf(Qs[(r0 + 8) * 132 + c0 + 4]);
    }

    float o_acc[16][4];
    #pragma unroll
    for (int nt = 0; nt < 16; nt++)
        #pragma unroll
        for (int e = 0; e < 4; e++) o_acc[nt][e] = 0.f;
    float m_i[2] = {-INFINITY, -INFINITY};
    float l_i[2] = {0.f, 0.f};

    const float scale = 0.08838834764831845f;  // 1/sqrt(128)
    const int ktiles = m0 / 64 + 1;            // causal: keys up to query pos

    for (int kt = 0; kt < ktiles; kt++) {
        int k0 = kt * 64;
        __syncthreads();  // previous iter's Vs/Ps consumers done
        for (int i = tid; i < 64 * 32; i += 128) {
            int r = i >> 5, c4 = i & 31;
            const float* kp = &kv[(size_t)(b * T_ + k0 + r) * 2048 + kvh * 128];
            *(float4*)&Ks[r * 132 + c4 * 4] = *(const float4*)&kp[c4 * 4];
            *(float4*)&Vs[r * 132 + c4 * 4] = *(const float4*)&kp[1024 + c4 * 4];
        }
        __syncthreads();

        // S = Q K^T  (warp: rows warp*16..+15, cols 0..63)
        float s[8][4];
        #pragma unroll
        for (int nt = 0; nt < 8; nt++)
            #pragma unroll
            for (int e = 0; e < 4; e++) s[nt][e] = 0.f;

        #pragma unroll 4
        for (int ks = 0; ks < 16; ks++) {
            #pragma unroll
            for (int nt = 0; nt < 8; nt++) {
                int cc = nt * 8 + gr;     // key index
                int rr = ks * 8 + tg;     // dim index
                uint32_t b0 = f2tf(Ks[cc * 132 + rr]);
                uint32_t b1 = f2tf(Ks[cc * 132 + rr + 4]);
                mma_tf32(s[nt], qf[ks], b0, b1);
            }
        }

        // scale + causal mask
        bool diag = (kt == ktiles - 1);
        #pragma unroll
        for (int nt = 0; nt < 8; nt++)
            #pragma unroll
            for (int e = 0; e < 4; e++) {
                int row = warp * 16 + gr + ((e >= 2) ? 8 : 0);
                int col = nt * 8 + 2 * tg + (e & 1);
                float v = s[nt][e] * scale;
                if (diag && (k0 + col > m0 + row)) v = -1e9f;
                s[nt][e] = v;
            }

        // online softmax: rows (gr) for e={0,1}, (gr+8) for e={2,3}
        #pragma unroll
        for (int half = 0; half < 2; half++) {
            float mx = -INFINITY;
            #pragma unroll
            for (int nt = 0; nt < 8; nt++) {
                mx = fmaxf(mx, s[nt][half * 2]);
                mx = fmaxf(mx, s[nt][half * 2 + 1]);
            }
            mx = fmaxf(mx, __shfl_xor_sync(0xffffffffu, mx, 1));
            mx = fmaxf(mx, __shfl_xor_sync(0xffffffffu, mx, 2));
            float mnew = fmaxf(m_i[half], mx);
            float corr = __expf(m_i[half] - mnew);
            float lsum = 0.f;
            #pragma unroll
            for (int nt = 0; nt < 8; nt++) {
                float e0 = __expf(s[nt][half * 2]     - mnew);
                float e1 = __expf(s[nt][half * 2 + 1] - mnew);
                s[nt][half * 2]     = e0;
                s[nt][half * 2 + 1] = e1;
                lsum += e0 + e1;
            }
            lsum += __shfl_xor_sync(0xffffffffu, lsum, 1);
            lsum += __shfl_xor_sync(0xffffffffu, lsum, 2);
            m_i[half] = mnew;
            l_i[half] = l_i[half] * corr + lsum;
            #pragma unroll
            for (int nt = 0; nt < 16; nt++) {
                o_acc[nt][half * 2]     *= corr;
                o_acc[nt][half * 2 + 1] *= corr;
            }
        }

        // P -> Ps (own warp rows only)
        #pragma unroll
        for (int nt = 0; nt < 8; nt++)
            #pragma unroll
            for (int e = 0; e < 4; e++) {
                int row = warp * 16 + gr + ((e >= 2) ? 8 : 0);
                int col = nt * 8 + 2 * tg + (e & 1);
                Ps[row * 68 + col] = s[nt][e];
            }
        __syncwarp();

        // O += P @ V   (A = P rows of this warp, 8 k-steps over 64 keys)
        #pragma unroll
        for (int ks = 0; ks < 8; ks++) {
            uint32_t pa[4];
            int r0 = warp * 16 + gr;
            int c0 = ks * 8 + tg;
            pa[0] = f2tf(Ps[r0 * 68 + c0]);
            pa[1] = f2tf(Ps[(r0 + 8) * 68 + c0]);
            pa[2] = f2tf(Ps[r0 * 68 + c0 + 4]);
            pa[3] = f2tf(Ps[(r0 + 8) * 68 + c0 + 4]);
            #pragma unroll
            for (int nt = 0; nt < 16; nt++) {
                uint32_t b0 = f2tf(Vs[(ks * 8 + tg) * 132 + nt * 8 + gr]);
                uint32_t b1 = f2tf(Vs[(ks * 8 + tg + 4) * 132 + nt * 8 + gr]);
                mma_tf32(o_acc[nt], pa, b0, b1);
            }
        }
    }

    // epilogue: out[n][h*128+d] = O / l
    #pragma unroll
    for (int nt = 0; nt < 16; nt++)
        #pragma unroll
        for (int e = 0; e < 4; e++) {
            int row = warp * 16 + gr + ((e >= 2) ? 8 : 0);
            int col = nt * 8 + 2 * tg + (e & 1);
            float inv_l = 1.f / l_i[(e >= 2) ? 1 : 0];
            out[((size_t)(b * T_ + m0 + row) * H_ + h) * HD_ + col] = o_acc[nt][e] * inv_l;
        }
}

// ---------------------------------------------------------------------------
// launch
// ---------------------------------------------------------------------------
extern "C" void kernel_launch(void* const* d_in, const int* in_sizes, int n_in,
                              void* d_out, int out_size) {
    const float* x    = (const float*)d_in[0];
    const float* w_q  = (const float*)d_in[1];
    const float* w_kv = (const float*)d_in[2];
    const float* w_o  = (const float*)d_in[3];
    const float* rcos = (const float*)d_in[6];
    const float* rsin = (const float*)d_in[7];
    const int* positions = (const int*)d_in[8];
    float* out = (float*)d_out;

    float *qb, *kvb, *ab;
    cudaGetSymbolAddress((void**)&qb,  g_q);
    cudaGetSymbolAddress((void**)&kvb, g_kv);
    cudaGetSymbolAddress((void**)&ab,  g_att);

    // Q and KV projections
    gemm_tf32_kernel<<<dim3(DM_ / GBN, NTOK / GBM), 256>>>(x, w_q,  qb,  NTOK, DM_,  DM_);
    gemm_tf32_kernel<<<dim3(2048 / GBN, NTOK / GBM), 256>>>(x, w_kv, kvb, NTOK, 2048, DM_);

    // RoPE on q and on k half of kv
    rope_kernel<<<(NTOK * H_   * 64) / 256, 256>>>(qb,  rcos, rsin, positions, H_,   DM_);
    rope_kernel<<<(NTOK * KVH_ * 64) / 256, 256>>>(kvb, rcos, rsin, positions, KVH_, 2048);

    // Attention
    int att_smem = ATT_SMEM_FLOATS * 4;
    cudaFuncSetAttribute(attn_kernel, cudaFuncAttributeMaxDynamicSharedMemorySize, att_smem);
    attn_kernel<<<dim3(T_ / 64, H_, B_), 128, att_smem>>>(qb, kvb, ab);

    // Output projection
    gemm_tf32_kernel<<<dim3(DM_ / GBN, NTOK / GBM), 256>>>(ab, w_o, out, NTOK, DM_, DM_);
}

// round 4
// speedup vs baseline: 1.3682x; 1.3682x over previous
#include <cuda_runtime.h>
#include <cstdint>
#include <cstddef>

#define B_   4
#define T_   1024
#define H_   32
#define KVH_ 8
#define HD_  128
#define DM_  4096
#define NTOK (B_ * T_)
#define KDIM 4096

// ---------------------------------------------------------------------------
// Scratch (device globals — no runtime allocation allowed)
// ---------------------------------------------------------------------------
__device__ float g_x  [(size_t)NTOK * DM_];    // rna(x)
__device__ float g_wqT [(size_t)DM_ * DM_];    // rna(w_q)^T  [N][K]
__device__ float g_wkvT[(size_t)2048 * DM_];   // rna(w_kv)^T [N][K]
__device__ float g_woT [(size_t)DM_ * DM_];    // rna(w_o)^T  [N][K]
__device__ float g_q  [(size_t)NTOK * DM_];    // q after proj+rope (rna)
__device__ float g_kv [(size_t)NTOK * 2048];   // [n][ k(8*128) | v(8*128) ] (rna)
__device__ float g_att[(size_t)NTOK * DM_];    // attention out (rna)

// ---------------------------------------------------------------------------
// helpers
// ---------------------------------------------------------------------------
__device__ __forceinline__ uint32_t f2tf(float x) {
    uint32_t r;
    asm("cvt.rna.tf32.f32 %0, %1;" : "=r"(r) : "f"(x));
    return r;
}

__device__ __forceinline__ uint32_t smem_u32(const void* p) {
    uint32_t a;
    asm("{ .reg .u64 t; cvta.to.shared.u64 t, %1; cvt.u32.u64 %0, t; }"
        : "=r"(a) : "l"(p));
    return a;
}

__device__ __forceinline__ void cp_async16(uint32_t dst, const float* src) {
    asm volatile("cp.async.cg.shared.global [%0], [%1], 16;\n"
                 :: "r"(dst), "l"(src) : "memory");
}
#define CP_COMMIT() asm volatile("cp.async.commit_group;\n" ::: "memory")
#define CP_WAIT(n)  asm volatile("cp.async.wait_group %0;\n" :: "n"(n) : "memory")

__device__ __forceinline__ void mma_tf32(float d[4], const uint32_t a[4],
                                         uint32_t b0, uint32_t b1) {
    asm volatile(
        "mma.sync.aligned.m16n8k8.row.col.f32.tf32.tf32.f32 "
        "{%0,%1,%2,%3}, {%4,%5,%6,%7}, {%8,%9}, {%0,%1,%2,%3};\n"
        : "+f"(d[0]), "+f"(d[1]), "+f"(d[2]), "+f"(d[3])
        : "r"(a[0]), "r"(a[1]), "r"(a[2]), "r"(a[3]), "r"(b0), "r"(b1));
}

// ---------------------------------------------------------------------------
// tf32 GEMM: C[M,N] = A[M,K] @ Bt[N,K]^T.  A, Bt pre-rounded to tf32.
// Block 256x128, BK=32, 256 threads (8 warps, 4x2), warp tile 64x64.
// 4-stage cp.async pipeline. Both smem tiles K-major [outer][36].
// ---------------------------------------------------------------------------
#define BM 256
#define BN 128
#define BK 32
#define NST 4
#define TS 36                          // smem row stride (floats)
#define A_TILE_F (BM * TS)             // 9216 floats
#define B_TILE_F (BN * TS)             // 4608 floats
#define STG_F (A_TILE_F + B_TILE_F)    // 13824 floats = 55296 B
#define GEMM_SMEM (NST * STG_F * 4)    // 221184 B

__global__ void __launch_bounds__(256, 1)
gemm_tc(const float* __restrict__ A, const float* __restrict__ Bt,
        float* __restrict__ C, int N) {
    extern __shared__ float sm[];
    const uint32_t sbase = smem_u32(sm);

    const int tid  = threadIdx.x;
    const int warp = tid >> 5;
    const int lane = tid & 31;
    const int wm = warp & 3;           // M: 4 warps
    const int wn = warp >> 2;          // N: 2 warps
    const int gr = lane >> 2;
    const int tg = lane & 3;
    const int m0 = blockIdx.y * BM;
    const int n0 = blockIdx.x * BN;
    const int NK = KDIM / BK;          // 128

    const float* aseg = A  + (size_t)m0 * KDIM;
    const float* bseg = Bt + (size_t)n0 * KDIM;

    // ---- stage loader (all 256 threads) ----
    auto load_stage = [&](int s, int kt) {
        const uint32_t dst = sbase + (uint32_t)(s * STG_F) * 4u;
        const int kf = kt * BK;
        #pragma unroll
        for (int p = 0; p < 8; p++) {               // A: 2048 float4
            int i = tid + p * 256;
            int row = i >> 3, u = i & 7;
            cp_async16(dst + (uint32_t)(row * TS + u * 4) * 4u,
                       aseg + (size_t)row * KDIM + kf + u * 4);
        }
        const uint32_t dstB = dst + (uint32_t)A_TILE_F * 4u;
        #pragma unroll
        for (int p = 0; p < 4; p++) {               // B: 1024 float4
            int i = tid + p * 256;
            int row = i >> 3, u = i & 7;
            cp_async16(dstB + (uint32_t)(row * TS + u * 4) * 4u,
                       bseg + (size_t)row * KDIM + kf + u * 4);
        }
        CP_COMMIT();
    };

    float acc[4][8][4];
    #pragma unroll
    for (int mt = 0; mt < 4; mt++)
        #pragma unroll
        for (int nt = 0; nt < 8; nt++)
            #pragma unroll
            for (int e = 0; e < 4; e++) acc[mt][nt][e] = 0.f;

    // prologue: fill 3 stages
    for (int s = 0; s < NST - 1; s++) load_stage(s, s);

    for (int kt = 0; kt < NK; kt++) {
        if (kt + NST - 1 < NK) CP_WAIT(NST - 2); else CP_WAIT(0);
        __syncthreads();
        if (kt + NST - 1 < NK) load_stage((kt + NST - 1) % NST, kt + NST - 1);

        const float* As = sm + (size_t)(kt % NST) * STG_F;
        const float* Bs = As + A_TILE_F;
        const float* Aw = As + (wm * 64 + gr) * TS;     // warp A base row
        const float* Bw = Bs + (wn * 64 + gr) * TS;     // warp B base row

        #pragma unroll
        for (int ks = 0; ks < 4; ks++) {
            const int c0 = ks * 8 + tg;
            uint32_t af[4][4];
            #pragma unroll
            for (int mt = 0; mt < 4; mt++) {
                const float* ap = Aw + mt * 16 * TS;
                af[mt][0] = __float_as_uint(ap[c0]);
                af[mt][1] = __float_as_uint(ap[8 * TS + c0]);
                af[mt][2] = __float_as_uint(ap[c0 + 4]);
                af[mt][3] = __float_as_uint(ap[8 * TS + c0 + 4]);
            }
            #pragma unroll
            for (int nt = 0; nt < 8; nt++) {
                const float* bp = Bw + nt * 8 * TS;
                uint32_t b0 = __float_as_uint(bp[c0]);
                uint32_t b1 = __float_as_uint(bp[c0 + 4]);
                #pragma unroll
                for (int mt = 0; mt < 4; mt++)
                    mma_tf32(acc[mt][nt], af[mt], b0, b1);
            }
        }
        __syncthreads();
    }

    // epilogue: 64-bit stores (adjacent e-pairs)
    #pragma unroll
    for (int mt = 0; mt < 4; mt++) {
        #pragma unroll
        for (int e2 = 0; e2 < 2; e2++) {
            int row = m0 + wm * 64 + mt * 16 + gr + e2 * 8;
            float* crow = C + (size_t)row * N + n0 + wn * 64;
            #pragma unroll
            for (int nt = 0; nt < 8; nt++) {
                float2 v;
                v.x = acc[mt][nt][e2 * 2];
                v.y = acc[mt][nt][e2 * 2 + 1];
                *(float2*)(crow + nt * 8 + 2 * tg) = v;
            }
        }
    }
}

// ---------------------------------------------------------------------------
// prep kernels
// ---------------------------------------------------------------------------
__global__ void round_x_kernel(const float* __restrict__ in, float* __restrict__ out,
                               int n4) {
    int i = blockIdx.x * blockDim.x + threadIdx.x;
    if (i >= n4) return;
    float4 v = ((const float4*)in)[i];
    v.x = __uint_as_float(f2tf(v.x));
    v.y = __uint_as_float(f2tf(v.y));
    v.z = __uint_as_float(f2tf(v.z));
    v.w = __uint_as_float(f2tf(v.w));
    ((float4*)out)[i] = v;
}

__global__ void transpose_rna_kernel(const float* __restrict__ W, float* __restrict__ Wt,
                                     int rows /*K*/, int cols /*N*/) {
    __shared__ float t[32][33];
    int bx = blockIdx.x * 32;
    int by = blockIdx.y * 32;
    int lx = threadIdx.x, ly = threadIdx.y;   // 32 x 8
    #pragma unroll
    for (int i = 0; i < 32; i += 8)
        t[ly + i][lx] = W[(size_t)(by + ly + i) * cols + bx + lx];
    __syncthreads();
    #pragma unroll
    for (int i = 0; i < 32; i += 8)
        Wt[(size_t)(bx + ly + i) * rows + by + lx] =
            __uint_as_float(f2tf(t[lx][ly + i]));
}

// round v half of g_kv in place: [n][1024..2047]
__global__ void round_v_kernel(float* __restrict__ kv) {
    int i = blockIdx.x * blockDim.x + threadIdx.x;   // float4 index
    if (i >= NTOK * 256) return;
    int n = i >> 8, c4 = i & 255;
    float4* p = (float4*)(kv + (size_t)n * 2048 + 1024 + c4 * 4);
    float4 v = *p;
    v.x = __uint_as_float(f2tf(v.x));
    v.y = __uint_as_float(f2tf(v.y));
    v.z = __uint_as_float(f2tf(v.z));
    v.w = __uint_as_float(f2tf(v.w));
    *p = v;
}

// ---------------------------------------------------------------------------
// RoPE (in place, writes rna-rounded)
// ---------------------------------------------------------------------------
__global__ void rope_kernel(float* __restrict__ buf, const float* __restrict__ rcos,
                            const float* __restrict__ rsin,
                            const int* __restrict__ positions,
                            int nheads, int rowstride) {
    int idx = blockIdx.x * blockDim.x + threadIdx.x;
    int total = NTOK * nheads * 64;
    if (idx >= total) return;
    int i = idx & 63;
    int h = (idx >> 6) % nheads;
    int n = idx / (64 * nheads);
    int pos = positions[n];
    float c = rcos[pos * 64 + i];
    float s = rsin[pos * 64 + i];
    float2* p = (float2*)(buf + (size_t)n * rowstride + h * 128 + 2 * i);
    float2 v = *p;
    float2 o;
    o.x = __uint_as_float(f2tf(v.x * c - v.y * s));
    o.y = __uint_as_float(f2tf(v.x * s + v.y * c));
    *p = o;
}

// ---------------------------------------------------------------------------
// Flash attention, causal, GQA, tf32 mma. All inputs pre-rounded to tf32.
// grid = (T/64, H, B), block = 128 (4 warps).
// ---------------------------------------------------------------------------
#define ATT_SMEM_FLOATS (3 * 64 * 132 + 64 * 68)

__global__ void __launch_bounds__(128)
attn_kernel(const float* __restrict__ q, const float* __restrict__ kv,
            float* __restrict__ out) {
    extern __shared__ float sm[];
    float* Qs = sm;
    float* Ks = Qs + 64 * 132;
    float* Vs = Ks + 64 * 132;
    float* Ps = Vs + 64 * 132;

    const int m0  = blockIdx.x * 64;
    const int h   = blockIdx.y;
    const int b   = blockIdx.z;
    const int kvh = h >> 2;
    const int tid  = threadIdx.x;
    const int warp = tid >> 5;
    const int lane = tid & 31;
    const int gr = lane >> 2;
    const int tg = lane & 3;

    for (int i = tid; i < 64 * 32; i += 128) {
        int r = i >> 5, c4 = i & 31;
        float4 v = *(const float4*)&q[((size_t)(b * T_ + m0 + r) * H_ + h) * HD_ + c4 * 4];
        *(float4*)&Qs[r * 132 + c4 * 4] = v;
    }
    __syncthreads();

    uint32_t qf[16][4];
    #pragma unroll
    for (int ks = 0; ks < 16; ks++) {
        int r0 = warp * 16 + gr;
        int c0 = ks * 8 + tg;
        qf[ks][0] = __float_as_uint(Qs[r0 * 132 + c0]);
        qf[ks][1] = __float_as_uint(Qs[(r0 + 8) * 132 + c0]);
        qf[ks][2] = __float_as_uint(Qs[r0 * 132 + c0 + 4]);
        qf[ks][3] = __float_as_uint(Qs[(r0 + 8) * 132 + c0 + 4]);
    }

    float o_acc[16][4];
    #pragma unroll
    for (int nt = 0; nt < 16; nt++)
        #pragma unroll
        for (int e = 0; e < 4; e++) o_acc[nt][e] = 0.f;
    float m_i[2] = {-INFINITY, -INFINITY};
    float l_i[2] = {0.f, 0.f};

    const float scale = 0.08838834764831845f;
    const int ktiles = m0 / 64 + 1;

    for (int kt = 0; kt < ktiles; kt++) {
        int k0 = kt * 64;
        __syncthreads();
        for (int i = tid; i < 64 * 32; i += 128) {
            int r = i >> 5, c4 = i & 31;
            const float* kp = &kv[(size_t)(b * T_ + k0 + r) * 2048 + kvh * 128];
            *(float4*)&Ks[r * 132 + c4 * 4] = *(const float4*)&kp[c4 * 4];
            *(float4*)&Vs[r * 132 + c4 * 4] = *(const float4*)&kp[1024 + c4 * 4];
        }
        __syncthreads();

        float s[8][4];
        #pragma unroll
        for (int nt = 0; nt < 8; nt++)
            #pragma unroll
            for (int e = 0; e < 4; e++) s[nt][e] = 0.f;

        #pragma unroll 4
        for (int ks = 0; ks < 16; ks++) {
            #pragma unroll
            for (int nt = 0; nt < 8; nt++) {
                int cc = nt * 8 + gr;
                int rr = ks * 8 + tg;
                uint32_t b0 = __float_as_uint(Ks[cc * 132 + rr]);
                uint32_t b1 = __float_as_uint(Ks[cc * 132 + rr + 4]);
                mma_tf32(s[nt], qf[ks], b0, b1);
            }
        }

        bool diag = (kt == ktiles - 1);
        #pragma unroll
        for (int nt = 0; nt < 8; nt++)
            #pragma unroll
            for (int e = 0; e < 4; e++) {
                int row = warp * 16 + gr + ((e >= 2) ? 8 : 0);
                int col = nt * 8 + 2 * tg + (e & 1);
                float v = s[nt][e] * scale;
                if (diag && (k0 + col > m0 + row)) v = -1e9f;
                s[nt][e] = v;
            }

        #pragma unroll
        for (int half = 0; half < 2; half++) {
            float mx = -INFINITY;
            #pragma unroll
            for (int nt = 0; nt < 8; nt++) {
                mx = fmaxf(mx, s[nt][half * 2]);
                mx = fmaxf(mx, s[nt][half * 2 + 1]);
            }
            mx = fmaxf(mx, __shfl_xor_sync(0xffffffffu, mx, 1));
            mx = fmaxf(mx, __shfl_xor_sync(0xffffffffu, mx, 2));
            float mnew = fmaxf(m_i[half], mx);
            float corr = __expf(m_i[half] - mnew);
            float lsum = 0.f;
            #pragma unroll
            for (int nt = 0; nt < 8; nt++) {
                float e0 = __expf(s[nt][half * 2]     - mnew);
                float e1 = __expf(s[nt][half * 2 + 1] - mnew);
                s[nt][half * 2]     = e0;
                s[nt][half * 2 + 1] = e1;
                lsum += e0 + e1;
            }
            lsum += __shfl_xor_sync(0xffffffffu, lsum, 1);
            lsum += __shfl_xor_sync(0xffffffffu, lsum, 2);
            m_i[half] = mnew;
            l_i[half] = l_i[half] * corr + lsum;
            #pragma unroll
            for (int nt = 0; nt < 16; nt++) {
                o_acc[nt][half * 2]     *= corr;
                o_acc[nt][half * 2 + 1] *= corr;
            }
        }

        // P -> Ps (rna-rounded once here; loads below are raw)
        #pragma unroll
        for (int nt = 0; nt < 8; nt++)
            #pragma unroll
            for (int e = 0; e < 4; e++) {
                int row = warp * 16 + gr + ((e >= 2) ? 8 : 0);
                int col = nt * 8 + 2 * tg + (e & 1);
                Ps[row * 68 + col] = __uint_as_float(f2tf(s[nt][e]));
            }
        __syncwarp();

        #pragma unroll
        for (int ks = 0; ks < 8; ks++) {
            uint32_t pa[4];
            int r0 = warp * 16 + gr;
            int c0 = ks * 8 + tg;
            pa[0] = __float_as_uint(Ps[r0 * 68 + c0]);
            pa[1] = __float_as_uint(Ps[(r0 + 8) * 68 + c0]);
            pa[2] = __float_as_uint(Ps[r0 * 68 + c0 + 4]);
            pa[3] = __float_as_uint(Ps[(r0 + 8) * 68 + c0 + 4]);
            #pragma unroll
            for (int nt = 0; nt < 16; nt++) {
                uint32_t b0 = __float_as_uint(Vs[(ks * 8 + tg) * 132 + nt * 8 + gr]);
                uint32_t b1 = __float_as_uint(Vs[(ks * 8 + tg + 4) * 132 + nt * 8 + gr]);
                mma_tf32(o_acc[nt], pa, b0, b1);
            }
        }
    }

    #pragma unroll
    for (int nt = 0; nt < 16; nt++)
        #pragma unroll
        for (int e = 0; e < 4; e++) {
            int row = warp * 16 + gr + ((e >= 2) ? 8 : 0);
            int col = nt * 8 + 2 * tg + (e & 1);
            float inv_l = 1.f / l_i[(e >= 2) ? 1 : 0];
            out[((size_t)(b * T_ + m0 + row) * H_ + h) * HD_ + col] =
                __uint_as_float(f2tf(o_acc[nt][e] * inv_l));
        }
}

// ---------------------------------------------------------------------------
// launch
// ---------------------------------------------------------------------------
extern "C" void kernel_launch(void* const* d_in, const int* in_sizes, int n_in,
                              void* d_out, int out_size) {
    const float* x    = (const float*)d_in[0];
    const float* w_q  = (const float*)d_in[1];
    const float* w_kv = (const float*)d_in[2];
    const float* w_o  = (const float*)d_in[3];
    const float* rcos = (const float*)d_in[6];
    const float* rsin = (const float*)d_in[7];
    const int* positions = (const int*)d_in[8];
    float* out = (float*)d_out;

    float *xb, *wqT, *wkvT, *woT, *qb, *kvb, *ab;
    cudaGetSymbolAddress((void**)&xb,   g_x);
    cudaGetSymbolAddress((void**)&wqT,  g_wqT);
    cudaGetSymbolAddress((void**)&wkvT, g_wkvT);
    cudaGetSymbolAddress((void**)&woT,  g_woT);
    cudaGetSymbolAddress((void**)&qb,   g_q);
    cudaGetSymbolAddress((void**)&kvb,  g_kv);
    cudaGetSymbolAddress((void**)&ab,   g_att);

    // prep: rna-round x; rna-round + transpose weights to [N][K]
    round_x_kernel<<<(NTOK * DM_ / 4 + 255) / 256, 256>>>(x, xb, NTOK * DM_ / 4);
    transpose_rna_kernel<<<dim3(DM_ / 32, DM_ / 32), dim3(32, 8)>>>(w_q, wqT, DM_, DM_);
    transpose_rna_kernel<<<dim3(2048 / 32, DM_ / 32), dim3(32, 8)>>>(w_kv, wkvT, DM_, 2048);
    transpose_rna_kernel<<<dim3(DM_ / 32, DM_ / 32), dim3(32, 8)>>>(w_o, woT, DM_, DM_);

    cudaFuncSetAttribute(gemm_tc, cudaFuncAttributeMaxDynamicSharedMemorySize, GEMM_SMEM);

    // Q and KV projections
    gemm_tc<<<dim3(DM_ / BN, NTOK / BM), 256, GEMM_SMEM>>>(xb, wqT, qb, DM_);
    gemm_tc<<<dim3(2048 / BN, NTOK / BM), 256, GEMM_SMEM>>>(xb, wkvT, kvb, 2048);

    // RoPE (writes rounded); round v half
    rope_kernel<<<(NTOK * H_   * 64) / 256, 256>>>(qb,  rcos, rsin, positions, H_,   DM_);
    rope_kernel<<<(NTOK * KVH_ * 64) / 256, 256>>>(kvb, rcos, rsin, positions, KVH_, 2048);
    round_v_kernel<<<(NTOK * 256 + 255) / 256, 256>>>(kvb);

    // Attention
    int att_smem = ATT_SMEM_FLOATS * 4;
    cudaFuncSetAttribute(attn_kernel, cudaFuncAttributeMaxDynamicSharedMemorySize, att_smem);
    attn_kernel<<<dim3(T_ / 64, H_, B_), 128, att_smem>>>(qb, kvb, ab);

    // Output projection
    gemm_tc<<<dim3(DM_ / BN, NTOK / BM), 256, GEMM_SMEM>>>(ab, woT, out, DM_);
}

// round 6
// speedup vs baseline: 1.4969x; 1.0941x over previous
#include <cuda_runtime.h>
#include <cstdint>
#include <cstddef>

#define B_   4
#define T_   1024
#define H_   32
#define KVH_ 8
#define HD_  128
#define DM_  4096
#define NTOK (B_ * T_)
#define KDIM 4096

// ---------------------------------------------------------------------------
// Scratch (device globals — no runtime allocation allowed)
// ---------------------------------------------------------------------------
__device__ float g_x  [(size_t)NTOK * DM_];    // rna(x)
__device__ float g_wqT [(size_t)DM_ * DM_];    // rna(w_q)^T  [N][K]
__device__ float g_wkvT[(size_t)2048 * DM_];   // rna(w_kv)^T [N][K]
__device__ float g_woT [(size_t)DM_ * DM_];    // rna(w_o)^T  [N][K]
__device__ float g_q  [(size_t)NTOK * DM_];    // q after proj+rope (rna)
__device__ float g_kv [(size_t)NTOK * 2048];   // [n][ k(8*128) | v(8*128) ] (rna)
__device__ float g_att[(size_t)NTOK * DM_];    // attention out (rna)

// ---------------------------------------------------------------------------
// helpers
// ---------------------------------------------------------------------------
__device__ __forceinline__ uint32_t f2tf(float x) {
    uint32_t r;
    asm("cvt.rna.tf32.f32 %0, %1;" : "=r"(r) : "f"(x));
    return r;
}

__device__ __forceinline__ uint32_t smem_u32(const void* p) {
    uint32_t a;
    asm("{ .reg .u64 t; cvta.to.shared.u64 t, %1; cvt.u32.u64 %0, t; }"
        : "=r"(a) : "l"(p));
    return a;
}

__device__ __forceinline__ void cp_async16(uint32_t dst, const float* src) {
    asm volatile("cp.async.cg.shared.global [%0], [%1], 16;\n"
                 :: "r"(dst), "l"(src) : "memory");
}
#define CP_COMMIT() asm volatile("cp.async.commit_group;\n" ::: "memory")
#define CP_WAIT(n)  asm volatile("cp.async.wait_group %0;\n" :: "n"(n) : "memory")

__device__ __forceinline__ void mma_tf32(float d[4], const uint32_t a[4],
                                         uint32_t b0, uint32_t b1) {
    asm volatile(
        "mma.sync.aligned.m16n8k8.row.col.f32.tf32.tf32.f32 "
        "{%0,%1,%2,%3}, {%4,%5,%6,%7}, {%8,%9}, {%0,%1,%2,%3};\n"
        : "+f"(d[0]), "+f"(d[1]), "+f"(d[2]), "+f"(d[3])
        : "r"(a[0]), "r"(a[1]), "r"(a[2]), "r"(a[3]), "r"(b0), "r"(b1));
}

// ---------------------------------------------------------------------------
// tf32 GEMM: C[M,N] = A[M,K] @ Bt[N,K]^T.  A, Bt pre-rounded to tf32.
// Block 256x128, BK=32, 256 threads (8 warps, 4x2), warp tile 64x64.
// 4-stage cp.async pipeline. Both smem tiles K-major [outer][36].
// ---------------------------------------------------------------------------
#define BM 256
#define BN 128
#define BK 32
#define NST 4
#define TS 36                          // smem row stride (floats)
#define A_TILE_F (BM * TS)             // 9216 floats
#define B_TILE_F (BN * TS)             // 4608 floats
#define STG_F (A_TILE_F + B_TILE_F)    // 13824 floats = 55296 B
#define GEMM_SMEM (NST * STG_F * 4)    // 221184 B

__global__ void __launch_bounds__(256, 1)
gemm_tc(const float* __restrict__ A, const float* __restrict__ Bt,
        float* __restrict__ C, int N) {
    extern __shared__ float sm[];
    const uint32_t sbase = smem_u32(sm);

    const int tid  = threadIdx.x;
    const int warp = tid >> 5;
    const int lane = tid & 31;
    const int wm = warp & 3;
    const int wn = warp >> 2;
    const int gr = lane >> 2;
    const int tg = lane & 3;
    const int m0 = blockIdx.y * BM;
    const int n0 = blockIdx.x * BN;
    const int NK = KDIM / BK;

    const float* aseg = A  + (size_t)m0 * KDIM;
    const float* bseg = Bt + (size_t)n0 * KDIM;

    auto load_stage = [&](int s, int kt) {
        const uint32_t dst = sbase + (uint32_t)(s * STG_F) * 4u;
        const int kf = kt * BK;
        #pragma unroll
        for (int p = 0; p < 8; p++) {
            int i = tid + p * 256;
            int row = i >> 3, u = i & 7;
            cp_async16(dst + (uint32_t)(row * TS + u * 4) * 4u,
                       aseg + (size_t)row * KDIM + kf + u * 4);
        }
        const uint32_t dstB = dst + (uint32_t)A_TILE_F * 4u;
        #pragma unroll
        for (int p = 0; p < 4; p++) {
            int i = tid + p * 256;
            int row = i >> 3, u = i & 7;
            cp_async16(dstB + (uint32_t)(row * TS + u * 4) * 4u,
                       bseg + (size_t)row * KDIM + kf + u * 4);
        }
        CP_COMMIT();
    };

    float acc[4][8][4];
    #pragma unroll
    for (int mt = 0; mt < 4; mt++)
        #pragma unroll
        for (int nt = 0; nt < 8; nt++)
            #pragma unroll
            for (int e = 0; e < 4; e++) acc[mt][nt][e] = 0.f;

    for (int s = 0; s < NST - 1; s++) load_stage(s, s);

    for (int kt = 0; kt < NK; kt++) {
        if (kt + NST - 1 < NK) CP_WAIT(NST - 2); else CP_WAIT(0);
        __syncthreads();
        if (kt + NST - 1 < NK) load_stage((kt + NST - 1) % NST, kt + NST - 1);

        const float* As = sm + (size_t)(kt % NST) * STG_F;
        const float* Bs = As + A_TILE_F;
        const float* Aw = As + (wm * 64 + gr) * TS;
        const float* Bw = Bs + (wn * 64 + gr) * TS;

        #pragma unroll
        for (int ks = 0; ks < 4; ks++) {
            const int c0 = ks * 8 + tg;
            uint32_t af[4][4];
            #pragma unroll
            for (int mt = 0; mt < 4; mt++) {
                const float* ap = Aw + mt * 16 * TS;
                af[mt][0] = __float_as_uint(ap[c0]);
                af[mt][1] = __float_as_uint(ap[8 * TS + c0]);
                af[mt][2] = __float_as_uint(ap[c0 + 4]);
                af[mt][3] = __float_as_uint(ap[8 * TS + c0 + 4]);
            }
            #pragma unroll
            for (int nt = 0; nt < 8; nt++) {
                const float* bp = Bw + nt * 8 * TS;
                uint32_t b0 = __float_as_uint(bp[c0]);
                uint32_t b1 = __float_as_uint(bp[c0 + 4]);
                #pragma unroll
                for (int mt = 0; mt < 4; mt++)
                    mma_tf32(acc[mt][nt], af[mt], b0, b1);
            }
        }
        __syncthreads();
    }

    #pragma unroll
    for (int mt = 0; mt < 4; mt++) {
        #pragma unroll
        for (int e2 = 0; e2 < 2; e2++) {
            int row = m0 + wm * 64 + mt * 16 + gr + e2 * 8;
            float* crow = C + (size_t)row * N + n0 + wn * 64;
            #pragma unroll
            for (int nt = 0; nt < 8; nt++) {
                float2 v;
                v.x = acc[mt][nt][e2 * 2];
                v.y = acc[mt][nt][e2 * 2 + 1];
                *(float2*)(crow + nt * 8 + 2 * tg) = v;
            }
        }
    }
}

// ---------------------------------------------------------------------------
// prep kernels
// ---------------------------------------------------------------------------
__global__ void round_x_kernel(const float* __restrict__ in, float* __restrict__ out,
                               int n4) {
    int i = blockIdx.x * blockDim.x + threadIdx.x;
    if (i >= n4) return;
    float4 v = ((const float4*)in)[i];
    v.x = __uint_as_float(f2tf(v.x));
    v.y = __uint_as_float(f2tf(v.y));
    v.z = __uint_as_float(f2tf(v.z));
    v.w = __uint_as_float(f2tf(v.w));
    ((float4*)out)[i] = v;
}

__global__ void transpose_rna_kernel(const float* __restrict__ W, float* __restrict__ Wt,
                                     int rows /*K*/, int cols /*N*/) {
    __shared__ float t[32][33];
    int bx = blockIdx.x * 32;
    int by = blockIdx.y * 32;
    int lx = threadIdx.x, ly = threadIdx.y;   // 32 x 8
    #pragma unroll
    for (int i = 0; i < 32; i += 8)
        t[ly + i][lx] = W[(size_t)(by + ly + i) * cols + bx + lx];
    __syncthreads();
    #pragma unroll
    for (int i = 0; i < 32; i += 8)
        Wt[(size_t)(bx + ly + i) * rows + by + lx] =
            __uint_as_float(f2tf(t[lx][ly + i]));
}

__global__ void round_v_kernel(float* __restrict__ kv) {
    int i = blockIdx.x * blockDim.x + threadIdx.x;   // float4 index
    if (i >= NTOK * 256) return;
    int n = i >> 8, c4 = i & 255;
    float4* p = (float4*)(kv + (size_t)n * 2048 + 1024 + c4 * 4);
    float4 v = *p;
    v.x = __uint_as_float(f2tf(v.x));
    v.y = __uint_as_float(f2tf(v.y));
    v.z = __uint_as_float(f2tf(v.z));
    v.w = __uint_as_float(f2tf(v.w));
    *p = v;
}

// ---------------------------------------------------------------------------
// RoPE (in place, writes rna-rounded)
// ---------------------------------------------------------------------------
__global__ void rope_kernel(float* __restrict__ buf, const float* __restrict__ rcos,
                            const float* __restrict__ rsin,
                            const int* __restrict__ positions,
                            int nheads, int rowstride) {
    int idx = blockIdx.x * blockDim.x + threadIdx.x;
    int total = NTOK * nheads * 64;
    if (idx >= total) return;
    int i = idx & 63;
    int h = (idx >> 6) % nheads;
    int n = idx / (64 * nheads);
    int pos = positions[n];
    float c = rcos[pos * 64 + i];
    float s = rsin[pos * 64 + i];
    float2* p = (float2*)(buf + (size_t)n * rowstride + h * 128 + 2 * i);
    float2 v = *p;
    float2 o;
    o.x = __uint_as_float(f2tf(v.x * c - v.y * s));
    o.y = __uint_as_float(f2tf(v.x * s + v.y * c));
    *p = o;
}

// ---------------------------------------------------------------------------
// Flash attention, causal, GQA, tf32 mma. All inputs pre-rounded to tf32.
// grid = (T/64, H, B), block = 128 (4 warps).
// smem: Ks[64*132] Vs[64*132] Qs[64*132]; P tile ALIASES Qs (Q rows are
// warp-private and dead after fragment extraction) -> 101KB -> 2 CTAs/SM.
// K/V tiles filled with cp.async.
// ---------------------------------------------------------------------------
#define ATT_SMEM_FLOATS (3 * 64 * 132)

__global__ void __launch_bounds__(128)
attn_kernel(const float* __restrict__ q, const float* __restrict__ kv,
            float* __restrict__ out) {
    extern __shared__ float sm[];
    float* Ks = sm;
    float* Vs = sm + 64 * 132;
    float* Qs = sm + 2 * 64 * 132;
    float* Ps = Qs;                    // alias: safe (per-warp rows)
    const uint32_t sK = smem_u32(Ks);
    const uint32_t sV = smem_u32(Vs);

    const int m0  = blockIdx.x * 64;
    const int h   = blockIdx.y;
    const int b   = blockIdx.z;
    const int kvh = h >> 2;
    const int tid  = threadIdx.x;
    const int warp = tid >> 5;
    const int lane = tid & 31;
    const int gr = lane >> 2;
    const int tg = lane & 3;

    for (int i = tid; i < 64 * 32; i += 128) {
        int r = i >> 5, c4 = i & 31;
        float4 v = *(const float4*)&q[((size_t)(b * T_ + m0 + r) * H_ + h) * HD_ + c4 * 4];
        *(float4*)&Qs[r * 132 + c4 * 4] = v;
    }
    __syncthreads();

    uint32_t qf[16][4];
    #pragma unroll
    for (int ks = 0; ks < 16; ks++) {
        int r0 = warp * 16 + gr;
        int c0 = ks * 8 + tg;
        qf[ks][0] = __float_as_uint(Qs[r0 * 132 + c0]);
        qf[ks][1] = __float_as_uint(Qs[(r0 + 8) * 132 + c0]);
        qf[ks][2] = __float_as_uint(Qs[r0 * 132 + c0 + 4]);
        qf[ks][3] = __float_as_uint(Qs[(r0 + 8) * 132 + c0 + 4]);
    }

    float o_acc[16][4];
    #pragma unroll
    for (int nt = 0; nt < 16; nt++)
        #pragma unroll
        for (int e = 0; e < 4; e++) o_acc[nt][e] = 0.f;
    float m_i[2] = {-INFINITY, -INFINITY};
    float l_i[2] = {0.f, 0.f};

    const float scale = 0.08838834764831845f;
    const int ktiles = m0 / 64 + 1;

    for (int kt = 0; kt < ktiles; kt++) {
        int k0 = kt * 64;
        __syncthreads();   // everyone done reading previous Ks/Vs
        // cp.async fill of K and V tiles (16 + 16 float4 per thread)
        {
            const float* base = &kv[(size_t)(b * T_ + k0) * 2048 + kvh * 128];
            #pragma unroll
            for (int p = 0; p < 16; p++) {
                int i = tid + p * 128;            // 0..2047
                int r = i >> 5, c4 = i & 31;
                uint32_t soff = (uint32_t)(r * 132 + c4 * 4) * 4u;
                const float* kp = base + (size_t)r * 2048;
                cp_async16(sK + soff, kp + c4 * 4);
                cp_async16(sV + soff, kp + 1024 + c4 * 4);
            }
            CP_COMMIT();
            CP_WAIT(0);
        }
        __syncthreads();

        float s[8][4];
        #pragma unroll
        for (int nt = 0; nt < 8; nt++)
            #pragma unroll
            for (int e = 0; e < 4; e++) s[nt][e] = 0.f;

        #pragma unroll 4
        for (int ks = 0; ks < 16; ks++) {
            #pragma unroll
            for (int nt = 0; nt < 8; nt++) {
                int cc = nt * 8 + gr;
                int rr = ks * 8 + tg;
                uint32_t b0 = __float_as_uint(Ks[cc * 132 + rr]);
                uint32_t b1 = __float_as_uint(Ks[cc * 132 + rr + 4]);
                mma_tf32(s[nt], qf[ks], b0, b1);
            }
        }

        bool diag = (kt == ktiles - 1);
        #pragma unroll
        for (int nt = 0; nt < 8; nt++)
            #pragma unroll
            for (int e = 0; e < 4; e++) {
                int row = warp * 16 + gr + ((e >= 2) ? 8 : 0);
                int col = nt * 8 + 2 * tg + (e & 1);
                float v = s[nt][e] * scale;
                if (diag && (k0 + col > m0 + row)) v = -1e9f;
                s[nt][e] = v;
            }

        #pragma unroll
        for (int half = 0; half < 2; half++) {
            float mx = -INFINITY;
            #pragma unroll
            for (int nt = 0; nt < 8; nt++) {
                mx = fmaxf(mx, s[nt][half * 2]);
                mx = fmaxf(mx, s[nt][half * 2 + 1]);
            }
            mx = fmaxf(mx, __shfl_xor_sync(0xffffffffu, mx, 1));
            mx = fmaxf(mx, __shfl_xor_sync(0xffffffffu, mx, 2));
            float mnew = fmaxf(m_i[half], mx);
            float corr = __expf(m_i[half] - mnew);
            float lsum = 0.f;
            #pragma unroll
            for (int nt = 0; nt < 8; nt++) {
                float e0 = __expf(s[nt][half * 2]     - mnew);
                float e1 = __expf(s[nt][half * 2 + 1] - mnew);
                s[nt][half * 2]     = e0;
                s[nt][half * 2 + 1] = e1;
                lsum += e0 + e1;
            }
            lsum += __shfl_xor_sync(0xffffffffu, lsum, 1);
            lsum += __shfl_xor_sync(0xffffffffu, lsum, 2);
            m_i[half] = mnew;
            l_i[half] = l_i[half] * corr + lsum;
            #pragma unroll
            for (int nt = 0; nt < 16; nt++) {
                o_acc[nt][half * 2]     *= corr;
                o_acc[nt][half * 2 + 1] *= corr;
            }
        }

        // P -> Ps (rna-rounded once; per-warp rows only)
        #pragma unroll
        for (int nt = 0; nt < 8; nt++)
            #pragma unroll
            for (int e = 0; e < 4; e++) {
                int row = warp * 16 + gr + ((e >= 2) ? 8 : 0);
                int col = nt * 8 + 2 * tg + (e & 1);
                Ps[row * 132 + col] = __uint_as_float(f2tf(s[nt][e]));
            }
        __syncwarp();

        #pragma unroll
        for (int ks = 0; ks < 8; ks++) {
            uint32_t pa[4];
            int r0 = warp * 16 + gr;
            int c0 = ks * 8 + tg;
            pa[0] = __float_as_uint(Ps[r0 * 132 + c0]);
            pa[1] = __float_as_uint(Ps[(r0 + 8) * 132 + c0]);
            pa[2] = __float_as_uint(Ps[r0 * 132 + c0 + 4]);
            pa[3] = __float_as_uint(Ps[(r0 + 8) * 132 + c0 + 4]);
            #pragma unroll
            for (int nt = 0; nt < 16; nt++) {
                uint32_t b0 = __float_as_uint(Vs[(ks * 8 + tg) * 132 + nt * 8 + gr]);
                uint32_t b1 = __float_as_uint(Vs[(ks * 8 + tg + 4) * 132 + nt * 8 + gr]);
                mma_tf32(o_acc[nt], pa, b0, b1);
            }
        }
    }

    #pragma unroll
    for (int nt = 0; nt < 16; nt++)
        #pragma unroll
        for (int e = 0; e < 4; e++) {
            int row = warp * 16 + gr + ((e >= 2) ? 8 : 0);
            int col = nt * 8 + 2 * tg + (e & 1);
            float inv_l = 1.f / l_i[(e >= 2) ? 1 : 0];
            out[((size_t)(b * T_ + m0 + row) * H_ + h) * HD_ + col] =
                __uint_as_float(f2tf(o_acc[nt][e] * inv_l));
        }
}

// ---------------------------------------------------------------------------
// launch — two streams, event fork/join (graph-capturable pattern)
// ---------------------------------------------------------------------------
extern "C" void kernel_launch(void* const* d_in, const int* in_sizes, int n_in,
                              void* d_out, int out_size) {
    const float* x    = (const float*)d_in[0];
    const float* w_q  = (const float*)d_in[1];
    const float* w_kv = (const float*)d_in[2];
    const float* w_o  = (const float*)d_in[3];
    const float* rcos = (const float*)d_in[6];
    const float* rsin = (const float*)d_in[7];
    const int* positions = (const int*)d_in[8];
    float* out = (float*)d_out;

    float *xb, *wqT, *wkvT, *woT, *qb, *kvb, *ab;
    cudaGetSymbolAddress((void**)&xb,   g_x);
    cudaGetSymbolAddress((void**)&wqT,  g_wqT);
    cudaGetSymbolAddress((void**)&wkvT, g_wkvT);
    cudaGetSymbolAddress((void**)&woT,  g_woT);
    cudaGetSymbolAddress((void**)&qb,   g_q);
    cudaGetSymbolAddress((void**)&kvb,  g_kv);
    cudaGetSymbolAddress((void**)&ab,   g_att);

    static cudaStream_t s1 = nullptr;
    static cudaEvent_t ev_start = nullptr, ev_rx = nullptr, ev_q = nullptr,
                       ev_wo = nullptr;
    if (s1 == nullptr) {
        cudaStreamCreateWithFlags(&s1, cudaStreamNonBlocking);
        cudaEventCreateWithFlags(&ev_start, cudaEventDisableTiming);
        cudaEventCreateWithFlags(&ev_rx,    cudaEventDisableTiming);
        cudaEventCreateWithFlags(&ev_q,     cudaEventDisableTiming);
        cudaEventCreateWithFlags(&ev_wo,    cudaEventDisableTiming);
        cudaFuncSetAttribute(gemm_tc,
            cudaFuncAttributeMaxDynamicSharedMemorySize, GEMM_SMEM);
        cudaFuncSetAttribute(attn_kernel,
            cudaFuncAttributeMaxDynamicSharedMemorySize, ATT_SMEM_FLOATS * 4);
    }

    // fork
    cudaEventRecord(ev_start, 0);
    cudaStreamWaitEvent(s1, ev_start, 0);

    // s0: round x, then KV chain
    round_x_kernel<<<(NTOK * DM_ / 4 + 255) / 256, 256>>>(x, xb, NTOK * DM_ / 4);
    cudaEventRecord(ev_rx, 0);
    transpose_rna_kernel<<<dim3(2048 / 32, DM_ / 32), dim3(32, 8)>>>(w_kv, wkvT, DM_, 2048);
    gemm_tc<<<dim3(2048 / BN, NTOK / BM), 256, GEMM_SMEM>>>(xb, wkvT, kvb, 2048);
    rope_kernel<<<(NTOK * KVH_ * 64) / 256, 256>>>(kvb, rcos, rsin, positions, KVH_, 2048);
    round_v_kernel<<<(NTOK * 256 + 255) / 256, 256>>>(kvb);

    // s1: Q chain (concurrent with KV chain) + w_o transpose
    transpose_rna_kernel<<<dim3(DM_ / 32, DM_ / 32), dim3(32, 8), 0, s1>>>(w_q, wqT, DM_, DM_);
    cudaStreamWaitEvent(s1, ev_rx, 0);
    gemm_tc<<<dim3(DM_ / BN, NTOK / BM), 256, GEMM_SMEM, s1>>>(xb, wqT, qb, DM_);
    rope_kernel<<<(NTOK * H_ * 64) / 256, 256, 0, s1>>>(qb, rcos, rsin, positions, H_, DM_);
    cudaEventRecord(ev_q, s1);
    transpose_rna_kernel<<<dim3(DM_ / 32, DM_ / 32), dim3(32, 8), 0, s1>>>(w_o, woT, DM_, DM_);
    cudaEventRecord(ev_wo, s1);

    // join: attention then O-projection on s0
    cudaStreamWaitEvent(0, ev_q, 0);
    attn_kernel<<<dim3(T_ / 64, H_, B_), 128, ATT_SMEM_FLOATS * 4>>>(qb, kvb, ab);
    cudaStreamWaitEvent(0, ev_wo, 0);
    gemm_tc<<<dim3(DM_ / BN, NTOK / BM), 256, GEMM_SMEM>>>(ab, woT, out, DM_);
}